// round 1
// baseline (speedup 1.0000x reference)
#include <cuda_runtime.h>
#include <math.h>

// Problem dims
#define B_ 8
#define L_ 512
#define D_ 512
#define H_ 8
#define DH_ 64
#define NROWS 4096          // B*L
#define NPAD 1664           // 512(q)+512(k)+512(v)+24(p) padded to 1664 (13*128)

// Output layout (concatenated fp32): readout | state_seq | mom_seq
#define OFF_S 2097152UL                    // B*L*H*DH
#define OFF_M 136314880UL                  // OFF_S + B*L*H*DH*DH

// Scratch (static device arrays — no allocation)
__device__ float g_W[D_ * NPAD];                    // packed [Wq|Wk|Wv|Wp|0pad]
__device__ float g_out[(size_t)NROWS * NPAD];       // projections
__device__ float g_gates[NROWS * 24];               // alpha[8] eta[8] theta[8] per row

// ---------------------------------------------------------------------------
// Kernel 1: pack weights into one [512 x 1664] matrix (zero-padded)
// ---------------------------------------------------------------------------
__global__ void pack_weights_kernel(const float* __restrict__ Wq,
                                    const float* __restrict__ Wk,
                                    const float* __restrict__ Wv,
                                    const float* __restrict__ Wp) {
    int idx = blockIdx.x * blockDim.x + threadIdx.x;
    if (idx >= D_ * NPAD) return;
    int d = idx / NPAD;
    int n = idx - d * NPAD;
    float v = 0.f;
    if (n < 512)       v = Wq[d * 512 + n];
    else if (n < 1024) v = Wk[d * 512 + (n - 512)];
    else if (n < 1536) v = Wv[d * 512 + (n - 1024)];
    else if (n < 1560) v = Wp[d * 24 + (n - 1536)];
    g_W[idx] = v;
}

// ---------------------------------------------------------------------------
// Kernel 2: SGEMM  C[4096,1664] = A[4096,512] * W[512,1664]
// 128x128 tile, BK=8, 256 threads, 8x8 per thread
// ---------------------------------------------------------------------------
__global__ __launch_bounds__(256) void sgemm_kernel(const float* __restrict__ A) {
    __shared__ float As[8][128];
    __shared__ float Bs[8][128];
    const int tid  = threadIdx.x;
    const int brow = blockIdx.y * 128;
    const int bcol = blockIdx.x * 128;
    const int arow = tid >> 1, acol = (tid & 1) * 4;   // A tile loader
    const int bro  = tid >> 5, bco  = (tid & 31) * 4;  // B tile loader
    const int tx   = tid & 15, ty   = tid >> 4;        // 16x16 thread grid

    float acc[8][8];
#pragma unroll
    for (int i = 0; i < 8; i++)
#pragma unroll
        for (int j = 0; j < 8; j++) acc[i][j] = 0.f;

    const float* Ap = A + (size_t)(brow + arow) * D_ + acol;
    const float* Bp = g_W + (size_t)bro * NPAD + bcol + bco;

    for (int k0 = 0; k0 < D_; k0 += 8) {
        float4 av = *(const float4*)Ap;
        float4 bv = *(const float4*)Bp;
        As[acol + 0][arow] = av.x;
        As[acol + 1][arow] = av.y;
        As[acol + 2][arow] = av.z;
        As[acol + 3][arow] = av.w;
        *(float4*)&Bs[bro][bco] = bv;
        __syncthreads();
#pragma unroll
        for (int kk = 0; kk < 8; kk++) {
            float ra[8], rb[8];
            *(float4*)&ra[0] = *(const float4*)&As[kk][ty * 8];
            *(float4*)&ra[4] = *(const float4*)&As[kk][ty * 8 + 4];
            *(float4*)&rb[0] = *(const float4*)&Bs[kk][tx * 8];
            *(float4*)&rb[4] = *(const float4*)&Bs[kk][tx * 8 + 4];
#pragma unroll
            for (int i = 0; i < 8; i++)
#pragma unroll
                for (int j = 0; j < 8; j++)
                    acc[i][j] = fmaf(ra[i], rb[j], acc[i][j]);
        }
        __syncthreads();
        Ap += 8;
        Bp += 8 * NPAD;
    }

    float* Cp = g_out + (size_t)(brow + ty * 8) * NPAD + bcol + tx * 8;
#pragma unroll
    for (int i = 0; i < 8; i++) {
        *(float4*)(Cp + 0) = make_float4(acc[i][0], acc[i][1], acc[i][2], acc[i][3]);
        *(float4*)(Cp + 4) = make_float4(acc[i][4], acc[i][5], acc[i][6], acc[i][7]);
        Cp += NPAD;
    }
}

// ---------------------------------------------------------------------------
// Kernel 3: postproc — L2-normalize k per (row, head), compute gates
// grid: 4096 blocks x 64 threads
// ---------------------------------------------------------------------------
__global__ __launch_bounds__(64) void postproc_kernel(const float* __restrict__ bp) {
    const int row = blockIdx.x;
    float* base = g_out + (size_t)row * NPAD;
    const int t  = threadIdx.x;
    const int hh = t >> 3, e8 = t & 7;

    float* kb = base + 512 + hh * 64 + e8 * 8;
    float kv[8];
    *(float4*)&kv[0] = *(const float4*)(kb + 0);
    *(float4*)&kv[4] = *(const float4*)(kb + 4);
    float ss = 0.f;
#pragma unroll
    for (int u = 0; u < 8; u++) ss = fmaf(kv[u], kv[u], ss);
    ss += __shfl_xor_sync(0xffffffffu, ss, 1);
    ss += __shfl_xor_sync(0xffffffffu, ss, 2);
    ss += __shfl_xor_sync(0xffffffffu, ss, 4);
    float scale = 1.0f / fmaxf(sqrtf(ss), 1e-12f);
#pragma unroll
    for (int u = 0; u < 8; u++) kv[u] *= scale;
    *(float4*)(kb + 0) = *(float4*)&kv[0];
    *(float4*)(kb + 4) = *(float4*)&kv[4];

    if (t < 24) {
        float p = base[1536 + t] + bp[t];
        float g;
        if (t < 16)       g = 1.0f / (1.0f + expf(-p));      // sigmoid: alpha, eta
        else              g = (p > 20.f) ? p : log1pf(expf(p)); // softplus: theta
        g_gates[row * 24 + t] = g;
    }
}

// ---------------------------------------------------------------------------
// Kernel 4: recurrence. grid = B*H*8 = 512 CTAs x 32 threads.
// CTA handles 8 rows of one (b,h) state. lane = r*4 + c:
//   r in [0,8) = row within block, c in [0,4) = 16-column group.
// State/momentum live in registers (16+16 floats per thread).
// ---------------------------------------------------------------------------
__global__ __launch_bounds__(32) void recurrence_kernel(const float* __restrict__ prev_state,
                                                        const float* __restrict__ prev_mom,
                                                        float* __restrict__ out) {
    const int bid = blockIdx.x;
    const int rb  = bid & 7;
    const int h   = (bid >> 3) & 7;
    const int b   = bid >> 6;
    const int lane = threadIdx.x;
    const int r = lane >> 2, c = lane & 3;
    const int gi = rb * 8 + r;                  // global row index in [0,64)

    float s[16], m[16];
    {
        const size_t off = ((size_t)((b * 8 + h) * 64 + gi)) * 64 + c * 16;
        const float* ps = prev_state + off;
        const float* pm = prev_mom + off;
#pragma unroll
        for (int u = 0; u < 16; u += 4) {
            *(float4*)&s[u] = *(const float4*)(ps + u);
            *(float4*)&m[u] = *(const float4*)(pm + u);
        }
    }

    const float* rowp = g_out + (size_t)(b * 512) * NPAD;
    const float* gp   = g_gates + (size_t)(b * 512) * 24;
    float* ro  = out + ((size_t)(b * 512) * 8 + h) * 64;
    float* ssq = out + OFF_S + ((size_t)(b * 512) * 8 + h) * 4096 + (size_t)gi * 64 + c * 16;
    float* msq = out + OFF_M + ((size_t)(b * 512) * 8 + h) * 4096 + (size_t)gi * 64 + c * 16;

    const int qoff = h * 64 + c * 16;
    const int koff = 512 + h * 64 + c * 16;
    const int voff = 1024 + h * 64 + gi;

    // prologue load (step 0)
    float ka[16], qa[16], va;
#pragma unroll
    for (int u = 0; u < 16; u += 4) {
        *(float4*)&qa[u] = *(const float4*)(rowp + qoff + u);
        *(float4*)&ka[u] = *(const float4*)(rowp + koff + u);
    }
    va = rowp[voff];

    for (int l = 0; l < 512; ++l) {
        // prefetch next step's q,k,v (clamped — re-reading last row is harmless)
        const float* nrow = rowp + ((l < 511) ? NPAD : 0);
        float kb_[16], qb_[16], vb_;
#pragma unroll
        for (int u = 0; u < 16; u += 4) {
            *(float4*)&qb_[u] = *(const float4*)(nrow + qoff + u);
            *(float4*)&kb_[u] = *(const float4*)(nrow + koff + u);
        }
        vb_ = nrow[voff];

        const float a  = gp[h];
        const float e  = gp[8 + h];
        const float th = gp[16 + h];

        // partial dot products over owned 16 columns
        float pv = 0.f, py = 0.f;
#pragma unroll
        for (int u = 0; u < 16; u++) {
            pv = fmaf(s[u], ka[u], pv);
            py = fmaf(s[u], qa[u], py);
        }
        // reduce across the 4 column-group lanes (xor bits 0,1 stay within c-group)
        pv += __shfl_xor_sync(0xffffffffu, pv, 1);
        pv += __shfl_xor_sync(0xffffffffu, pv, 2);
        py += __shfl_xor_sync(0xffffffffu, py, 1);
        py += __shfl_xor_sync(0xffffffffu, py, 2);

        if (c == 0) ro[gi] = py;   // readout uses PRE-update state

        const float d   = pv - va;
        const float td  = th * d;
        const float oma = 1.0f - a;
#pragma unroll
        for (int u = 0; u < 16; u++) {
            m[u] = fmaf(e, m[u], -td * ka[u]);   // eta*mom - theta*grad
            s[u] = fmaf(oma, s[u], m[u]);        // (1-alpha)*state + mom
        }

        // streaming stores (keep qkv scratch resident in L2)
#pragma unroll
        for (int u = 0; u < 16; u += 4) {
            __stcs((float4*)(ssq + u), *(float4*)&s[u]);
            __stcs((float4*)(msq + u), *(float4*)&m[u]);
        }

#pragma unroll
        for (int u = 0; u < 16; u++) { ka[u] = kb_[u]; qa[u] = qb_[u]; }
        va = vb_;

        rowp += NPAD;
        gp   += 24;
        ro   += 512;     // H*DH
        ssq  += 32768;   // H*DH*DH
        msq  += 32768;
    }
}

// ---------------------------------------------------------------------------
// Launch
// ---------------------------------------------------------------------------
extern "C" void kernel_launch(void* const* d_in, const int* in_sizes, int n_in,
                              void* d_out, int out_size) {
    const float* inputs   = (const float*)d_in[0];
    const float* Wq       = (const float*)d_in[1];
    const float* Wk       = (const float*)d_in[2];
    const float* Wv       = (const float*)d_in[3];
    const float* Wp       = (const float*)d_in[4];
    const float* bp       = (const float*)d_in[5];
    const float* prev_st  = (const float*)d_in[6];
    const float* prev_mom = (const float*)d_in[7];
    float* out = (float*)d_out;

    pack_weights_kernel<<<(D_ * NPAD + 255) / 256, 256>>>(Wq, Wk, Wv, Wp);
    sgemm_kernel<<<dim3(NPAD / 128, NROWS / 128), 256>>>(inputs);
    postproc_kernel<<<NROWS, 64>>>(bp);
    recurrence_kernel<<<B_ * H_ * 8, 32>>>(prev_st, prev_mom, out);
}

// round 2
// speedup vs baseline: 1.2093x; 1.2093x over previous
#include <cuda_runtime.h>
#include <math.h>

// Problem dims
#define B_ 8
#define L_ 512
#define D_ 512
#define H_ 8
#define DH_ 64
#define NROWS 4096          // B*L
#define NPAD 1664           // 512(q)+512(k)+512(v)+24(p) padded

// Output layout (concatenated fp32): readout | state_seq | mom_seq
#define OFF_S 2097152UL
#define OFF_M 136314880UL

// Packed per-(b,h) stream: [q(64) | k_norm(64) | v(64) | gates(4)] per step
#define PSTEP 196

// Scratch (static device arrays — no allocation)
__device__ float g_W[D_ * NPAD];                       // packed [Wq|Wk|Wv|Wp|0pad]
__device__ float g_out[(size_t)NROWS * NPAD];          // raw projections
__device__ float g_pack[(size_t)B_ * H_ * L_ * PSTEP]; // packed recurrence stream

// ---------------------------------------------------------------------------
// Kernel 1: pack weights into one [512 x 1664] matrix (zero-padded)
// ---------------------------------------------------------------------------
__global__ void pack_weights_kernel(const float* __restrict__ Wq,
                                    const float* __restrict__ Wk,
                                    const float* __restrict__ Wv,
                                    const float* __restrict__ Wp) {
    int idx = blockIdx.x * blockDim.x + threadIdx.x;
    if (idx >= D_ * NPAD) return;
    int d = idx / NPAD;
    int n = idx - d * NPAD;
    float v = 0.f;
    if (n < 512)       v = Wq[d * 512 + n];
    else if (n < 1024) v = Wk[d * 512 + (n - 512)];
    else if (n < 1536) v = Wv[d * 512 + (n - 1024)];
    else if (n < 1560) v = Wp[d * 24 + (n - 1536)];
    g_W[idx] = v;
}

// ---------------------------------------------------------------------------
// Kernel 2: SGEMM  C[4096,1664] = A[4096,512] * W[512,1664]
// 128x128 tile, BK=8, 256 threads, 8x8 per thread
// ---------------------------------------------------------------------------
__global__ __launch_bounds__(256) void sgemm_kernel(const float* __restrict__ A) {
    __shared__ float As[8][128];
    __shared__ float Bs[8][128];
    const int tid  = threadIdx.x;
    const int brow = blockIdx.y * 128;
    const int bcol = blockIdx.x * 128;
    const int arow = tid >> 1, acol = (tid & 1) * 4;
    const int bro  = tid >> 5, bco  = (tid & 31) * 4;
    const int tx   = tid & 15, ty   = tid >> 4;

    float acc[8][8];
#pragma unroll
    for (int i = 0; i < 8; i++)
#pragma unroll
        for (int j = 0; j < 8; j++) acc[i][j] = 0.f;

    const float* Ap = A + (size_t)(brow + arow) * D_ + acol;
    const float* Bp = g_W + (size_t)bro * NPAD + bcol + bco;

    for (int k0 = 0; k0 < D_; k0 += 8) {
        float4 av = *(const float4*)Ap;
        float4 bv = *(const float4*)Bp;
        As[acol + 0][arow] = av.x;
        As[acol + 1][arow] = av.y;
        As[acol + 2][arow] = av.z;
        As[acol + 3][arow] = av.w;
        *(float4*)&Bs[bro][bco] = bv;
        __syncthreads();
#pragma unroll
        for (int kk = 0; kk < 8; kk++) {
            float ra[8], rb[8];
            *(float4*)&ra[0] = *(const float4*)&As[kk][ty * 8];
            *(float4*)&ra[4] = *(const float4*)&As[kk][ty * 8 + 4];
            *(float4*)&rb[0] = *(const float4*)&Bs[kk][tx * 8];
            *(float4*)&rb[4] = *(const float4*)&Bs[kk][tx * 8 + 4];
#pragma unroll
            for (int i = 0; i < 8; i++)
#pragma unroll
                for (int j = 0; j < 8; j++)
                    acc[i][j] = fmaf(ra[i], rb[j], acc[i][j]);
        }
        __syncthreads();
        Ap += 8;
        Bp += 8 * NPAD;
    }

    float* Cp = g_out + (size_t)(brow + ty * 8) * NPAD + bcol + tx * 8;
#pragma unroll
    for (int i = 0; i < 8; i++) {
        *(float4*)(Cp + 0) = make_float4(acc[i][0], acc[i][1], acc[i][2], acc[i][3]);
        *(float4*)(Cp + 4) = make_float4(acc[i][4], acc[i][5], acc[i][6], acc[i][7]);
        Cp += NPAD;
    }
}

// ---------------------------------------------------------------------------
// Kernel 3: postproc — normalize k, compute gates, repack into per-(b,h)
// contiguous stream g_pack[b][h][l] = [q64 | k64 | v64 | a,e,th,0]
// grid: 4096 rows x 64 threads. Thread (hh = t>>3, e8 = t&7) owns 8 elems.
// ---------------------------------------------------------------------------
__global__ __launch_bounds__(64) void postproc_kernel(const float* __restrict__ bp) {
    const int row = blockIdx.x;
    const int b = row >> 9, l = row & 511;
    const float* base = g_out + (size_t)row * NPAD;
    const int t  = threadIdx.x;
    const int hh = t >> 3, e8 = t & 7;

    __shared__ float sg[24];
    if (t < 24) {
        float p = base[1536 + t] + bp[t];
        sg[t] = (t < 16) ? (1.0f / (1.0f + expf(-p)))
                         : ((p > 20.f) ? p : log1pf(expf(p)));
    }

    float* dst = g_pack + ((size_t)(b * 8 + hh) * 512 + l) * PSTEP;

    // k: normalize and write
    float kv[8];
    const float* kb = base + 512 + hh * 64 + e8 * 8;
    *(float4*)&kv[0] = *(const float4*)(kb + 0);
    *(float4*)&kv[4] = *(const float4*)(kb + 4);
    float ss = 0.f;
#pragma unroll
    for (int u = 0; u < 8; u++) ss = fmaf(kv[u], kv[u], ss);
    ss += __shfl_xor_sync(0xffffffffu, ss, 1);
    ss += __shfl_xor_sync(0xffffffffu, ss, 2);
    ss += __shfl_xor_sync(0xffffffffu, ss, 4);
    float scale = 1.0f / fmaxf(sqrtf(ss), 1e-12f);
#pragma unroll
    for (int u = 0; u < 8; u++) kv[u] *= scale;
    *(float4*)(dst + 64 + e8 * 8 + 0) = *(float4*)&kv[0];
    *(float4*)(dst + 64 + e8 * 8 + 4) = *(float4*)&kv[4];

    // q copy
    const float* qb = base + hh * 64 + e8 * 8;
    *(float4*)(dst + e8 * 8 + 0) = *(const float4*)(qb + 0);
    *(float4*)(dst + e8 * 8 + 4) = *(const float4*)(qb + 4);

    // v copy
    const float* vb = base + 1024 + hh * 64 + e8 * 8;
    *(float4*)(dst + 128 + e8 * 8 + 0) = *(const float4*)(vb + 0);
    *(float4*)(dst + 128 + e8 * 8 + 4) = *(const float4*)(vb + 4);

    __syncthreads();
    if (e8 < 4) dst[192 + e8] = (e8 < 3) ? sg[e8 * 8 + hh] : 0.f;
}

// ---------------------------------------------------------------------------
// Kernel 4: recurrence. grid = B*H*16 = 1024 CTAs x 64 threads (2048 warps).
// CTA handles 4 rows of one (b,h) state. Thread (r = t>>4, c = t&15) owns
// 4 columns: s[4], m[4] in registers. 16-lane shfl reductions per row.
// ---------------------------------------------------------------------------
__global__ __launch_bounds__(64) void recurrence_kernel(const float* __restrict__ prev_state,
                                                        const float* __restrict__ prev_mom,
                                                        float* __restrict__ out) {
    const int bid = blockIdx.x;
    const int rb  = bid & 15;
    const int h   = (bid >> 4) & 7;
    const int b   = bid >> 7;
    const int t   = threadIdx.x;
    const int r = t >> 4, c = t & 15;
    const int gi = rb * 4 + r;                  // global state row in [0,64)

    float s[4], m[4];
    {
        const size_t off = ((size_t)((b * 8 + h) * 64 + gi)) * 64 + c * 4;
        *(float4*)&s[0] = *(const float4*)(prev_state + off);
        *(float4*)&m[0] = *(const float4*)(prev_mom + off);
    }

    const float* pk = g_pack + (size_t)((b * 8 + h) * 512) * PSTEP;
    float* ro  = out + ((size_t)(b * 512) * 8 + h) * 64 + gi;
    float* ssq = out + OFF_S + ((size_t)(b * 512) * 8 + h) * 4096 + (size_t)gi * 64 + c * 4;
    float* msq = ssq + (OFF_M - OFF_S);

    // prologue load (step 0)
    float qa[4], ka[4];
    float va;
    float4 ga;
    *(float4*)&qa[0] = *(const float4*)(pk + c * 4);
    *(float4*)&ka[0] = *(const float4*)(pk + 64 + c * 4);
    va = pk[128 + gi];
    ga = *(const float4*)(pk + 192);

    for (int l = 0; l < 512; ++l) {
        // prefetch next step (clamped on the last iteration)
        const float* np = pk + ((l < 511) ? PSTEP : 0);
        float qb_[4], kb_[4], vb_;
        float4 gb_;
        *(float4*)&qb_[0] = *(const float4*)(np + c * 4);
        *(float4*)&kb_[0] = *(const float4*)(np + 64 + c * 4);
        vb_ = np[128 + gi];
        gb_ = *(const float4*)(np + 192);

        // partial dot products over owned 4 columns
        float pv = 0.f, py = 0.f;
#pragma unroll
        for (int u = 0; u < 4; u++) {
            pv = fmaf(s[u], ka[u], pv);
            py = fmaf(s[u], qa[u], py);
        }
        // reduce over the 16 lanes of this row
        pv += __shfl_xor_sync(0xffffffffu, pv, 1);
        py += __shfl_xor_sync(0xffffffffu, py, 1);
        pv += __shfl_xor_sync(0xffffffffu, pv, 2);
        py += __shfl_xor_sync(0xffffffffu, py, 2);
        pv += __shfl_xor_sync(0xffffffffu, pv, 4);
        py += __shfl_xor_sync(0xffffffffu, py, 4);
        pv += __shfl_xor_sync(0xffffffffu, pv, 8);
        py += __shfl_xor_sync(0xffffffffu, py, 8);

        if (c == 0) *ro = py;     // readout uses PRE-update state

        const float d   = pv - va;
        const float td  = ga.z * d;
        const float oma = 1.0f - ga.x;
        const float e   = ga.y;
#pragma unroll
        for (int u = 0; u < 4; u++) {
            m[u] = fmaf(e, m[u], -td * ka[u]);   // eta*mom - theta*grad
            s[u] = fmaf(oma, s[u], m[u]);        // (1-alpha)*state + mom
        }

        __stcs((float4*)ssq, *(float4*)&s[0]);
        __stcs((float4*)msq, *(float4*)&m[0]);

#pragma unroll
        for (int u = 0; u < 4; u++) { ka[u] = kb_[u]; qa[u] = qb_[u]; }
        va = vb_;
        ga = gb_;

        pk  += PSTEP;
        ro  += 512;      // H*DH
        ssq += 32768;    // H*DH*DH
        msq += 32768;
    }
}

// ---------------------------------------------------------------------------
// Launch
// ---------------------------------------------------------------------------
extern "C" void kernel_launch(void* const* d_in, const int* in_sizes, int n_in,
                              void* d_out, int out_size) {
    const float* inputs   = (const float*)d_in[0];
    const float* Wq       = (const float*)d_in[1];
    const float* Wk       = (const float*)d_in[2];
    const float* Wv       = (const float*)d_in[3];
    const float* Wp       = (const float*)d_in[4];
    const float* bp       = (const float*)d_in[5];
    const float* prev_st  = (const float*)d_in[6];
    const float* prev_mom = (const float*)d_in[7];
    float* out = (float*)d_out;

    pack_weights_kernel<<<(D_ * NPAD + 255) / 256, 256>>>(Wq, Wk, Wv, Wp);
    sgemm_kernel<<<dim3(NPAD / 128, NROWS / 128), 256>>>(inputs);
    postproc_kernel<<<NROWS, 64>>>(bp);
    recurrence_kernel<<<B_ * H_ * 16, 64>>>(prev_st, prev_mom, out);
}

// round 5
// speedup vs baseline: 1.4388x; 1.1898x over previous
#include <cuda_runtime.h>
#include <math.h>

// Problem dims
#define B_ 8
#define L_ 512
#define D_ 512
#define H_ 8
#define DH_ 64
#define NROWS 4096          // B*L
#define NPAD 1664           // 512(q)+512(k)+512(v)+24(p) padded

// Output layout (concatenated fp32): readout | state_seq | mom_seq
#define OFF_S 2097152UL
#define OFF_M 136314880UL

// Packed per-(b,h) stream: [q(64) | k_norm(64) | v(64) | gates(4)] per step
#define PSTEP 196

// Scratch (static device arrays — no allocation)
__device__ float g_W[D_ * NPAD];                       // packed [Wq|Wk|Wv|Wp|0pad]
__device__ float g_out[(size_t)NROWS * NPAD];          // raw projections
__device__ float g_pack[(size_t)B_ * H_ * L_ * PSTEP]; // packed recurrence stream

// ---------------------------------------------------------------------------
// Kernel 1: pack weights into one [512 x 1664] matrix (zero-padded)
// ---------------------------------------------------------------------------
__global__ void pack_weights_kernel(const float* __restrict__ Wq,
                                    const float* __restrict__ Wk,
                                    const float* __restrict__ Wv,
                                    const float* __restrict__ Wp) {
    int idx = blockIdx.x * blockDim.x + threadIdx.x;
    if (idx >= D_ * NPAD) return;
    int d = idx / NPAD;
    int n = idx - d * NPAD;
    float v = 0.f;
    if (n < 512)       v = Wq[d * 512 + n];
    else if (n < 1024) v = Wk[d * 512 + (n - 512)];
    else if (n < 1536) v = Wv[d * 512 + (n - 1024)];
    else if (n < 1560) v = Wp[d * 24 + (n - 1536)];
    g_W[idx] = v;
}

// ---------------------------------------------------------------------------
// Kernel 2: SGEMM  C[4096,1664] = A[4096,512] * W[512,1664]
// 128x128 tile, BK=8, 256 threads, 8x8 per thread
// ---------------------------------------------------------------------------
__global__ __launch_bounds__(256) void sgemm_kernel(const float* __restrict__ A) {
    __shared__ float As[8][128];
    __shared__ float Bs[8][128];
    const int tid  = threadIdx.x;
    const int brow = blockIdx.y * 128;
    const int bcol = blockIdx.x * 128;
    const int arow = tid >> 1, acol = (tid & 1) * 4;
    const int bro  = tid >> 5, bco  = (tid & 31) * 4;
    const int tx   = tid & 15, ty   = tid >> 4;

    float acc[8][8];
#pragma unroll
    for (int i = 0; i < 8; i++)
#pragma unroll
        for (int j = 0; j < 8; j++) acc[i][j] = 0.f;

    const float* Ap = A + (size_t)(brow + arow) * D_ + acol;
    const float* Bp = g_W + (size_t)bro * NPAD + bcol + bco;

    for (int k0 = 0; k0 < D_; k0 += 8) {
        float4 av = *(const float4*)Ap;
        float4 bv = *(const float4*)Bp;
        As[acol + 0][arow] = av.x;
        As[acol + 1][arow] = av.y;
        As[acol + 2][arow] = av.z;
        As[acol + 3][arow] = av.w;
        *(float4*)&Bs[bro][bco] = bv;
        __syncthreads();
#pragma unroll
        for (int kk = 0; kk < 8; kk++) {
            float ra[8], rb[8];
            *(float4*)&ra[0] = *(const float4*)&As[kk][ty * 8];
            *(float4*)&ra[4] = *(const float4*)&As[kk][ty * 8 + 4];
            *(float4*)&rb[0] = *(const float4*)&Bs[kk][tx * 8];
            *(float4*)&rb[4] = *(const float4*)&Bs[kk][tx * 8 + 4];
#pragma unroll
            for (int i = 0; i < 8; i++)
#pragma unroll
                for (int j = 0; j < 8; j++)
                    acc[i][j] = fmaf(ra[i], rb[j], acc[i][j]);
        }
        __syncthreads();
        Ap += 8;
        Bp += 8 * NPAD;
    }

    float* Cp = g_out + (size_t)(brow + ty * 8) * NPAD + bcol + tx * 8;
#pragma unroll
    for (int i = 0; i < 8; i++) {
        *(float4*)(Cp + 0) = make_float4(acc[i][0], acc[i][1], acc[i][2], acc[i][3]);
        *(float4*)(Cp + 4) = make_float4(acc[i][4], acc[i][5], acc[i][6], acc[i][7]);
        Cp += NPAD;
    }
}

// ---------------------------------------------------------------------------
// Kernel 3: postproc — normalize k, compute gates, repack into per-(b,h)
// contiguous stream g_pack[b][h][l] = [q64 | k64 | v64 | a,e,th,0]
// ---------------------------------------------------------------------------
__global__ __launch_bounds__(64) void postproc_kernel(const float* __restrict__ bp) {
    const int row = blockIdx.x;
    const int b = row >> 9, l = row & 511;
    const float* base = g_out + (size_t)row * NPAD;
    const int t  = threadIdx.x;
    const int hh = t >> 3, e8 = t & 7;

    __shared__ float sg[24];
    if (t < 24) {
        float p = base[1536 + t] + bp[t];
        sg[t] = (t < 16) ? (1.0f / (1.0f + expf(-p)))
                         : ((p > 20.f) ? p : log1pf(expf(p)));
    }

    float* dst = g_pack + ((size_t)(b * 8 + hh) * 512 + l) * PSTEP;

    // k: normalize and write
    float kv[8];
    const float* kb = base + 512 + hh * 64 + e8 * 8;
    *(float4*)&kv[0] = *(const float4*)(kb + 0);
    *(float4*)&kv[4] = *(const float4*)(kb + 4);
    float ss = 0.f;
#pragma unroll
    for (int u = 0; u < 8; u++) ss = fmaf(kv[u], kv[u], ss);
    ss += __shfl_xor_sync(0xffffffffu, ss, 1);
    ss += __shfl_xor_sync(0xffffffffu, ss, 2);
    ss += __shfl_xor_sync(0xffffffffu, ss, 4);
    float scale = 1.0f / fmaxf(sqrtf(ss), 1e-12f);
#pragma unroll
    for (int u = 0; u < 8; u++) kv[u] *= scale;
    *(float4*)(dst + 64 + e8 * 8 + 0) = *(float4*)&kv[0];
    *(float4*)(dst + 64 + e8 * 8 + 4) = *(float4*)&kv[4];

    // q copy
    const float* qb = base + hh * 64 + e8 * 8;
    *(float4*)(dst + e8 * 8 + 0) = *(const float4*)(qb + 0);
    *(float4*)(dst + e8 * 8 + 4) = *(const float4*)(qb + 4);

    // v copy
    const float* vb = base + 1024 + hh * 64 + e8 * 8;
    *(float4*)(dst + 128 + e8 * 8 + 0) = *(const float4*)(vb + 0);
    *(float4*)(dst + 128 + e8 * 8 + 4) = *(const float4*)(vb + 4);

    __syncthreads();
    if (e8 < 4) dst[192 + e8] = (e8 < 3) ? sg[e8 * 8 + hh] : 0.f;
}

// ---------------------------------------------------------------------------
// Kernel 4: recurrence. grid = B*H*16 = 1024 CTAs x 64 threads (2048 warps).
// CTA handles 4 rows of one (b,h). Thread (r = t>>4, c = t&15) owns 4 cols.
// 4-deep register ring with prefetch distance 3 to cover L2/DRAM latency.
// ---------------------------------------------------------------------------
__global__ __launch_bounds__(64) void recurrence_kernel(const float* __restrict__ prev_state,
                                                        const float* __restrict__ prev_mom,
                                                        float* __restrict__ out) {
    const int bid = blockIdx.x;
    const int rb  = bid & 15;
    const int h   = (bid >> 4) & 7;
    const int b   = bid >> 7;
    const int t   = threadIdx.x;
    const int r = t >> 4, c = t & 15;
    const int gi = rb * 4 + r;                  // global state row in [0,64)

    float s[4], m[4];
    {
        const size_t off = ((size_t)((b * 8 + h) * 64 + gi)) * 64 + c * 4;
        *(float4*)&s[0] = *(const float4*)(prev_state + off);
        *(float4*)&m[0] = *(const float4*)(prev_mom + off);
    }

    const float* pbh = g_pack + (size_t)((b * 8 + h) * 512) * PSTEP;
    float* ro  = out + ((size_t)(b * 512) * 8 + h) * 64 + gi;
    float* ssq = out + OFF_S + ((size_t)(b * 512) * 8 + h) * 4096 + (size_t)gi * 64 + c * 4;
    float* msq = ssq + (OFF_M - OFF_S);

    // 4-deep prefetch ring (q, k, v, gates)
    float qb[4][4], kb[4][4], vb[4];
    float4 gb[4];
#pragma unroll
    for (int p = 0; p < 3; p++) {
        const float* sp = pbh + p * PSTEP;
        *(float4*)qb[p] = *(const float4*)(sp + c * 4);
        *(float4*)kb[p] = *(const float4*)(sp + 64 + c * 4);
        vb[p] = sp[128 + gi];
        gb[p] = *(const float4*)(sp + 192);
    }

#pragma unroll 4
    for (int l = 0; l < 512; ++l) {
        const int bi = l & 3;
        const int pi = (l + 3) & 3;
        const int pl = (l + 3 < 512) ? (l + 3) : 511;
        const float* sp = pbh + (size_t)pl * PSTEP;
        // prefetch step l+3 into ring slot pi (never collides with bi)
        *(float4*)qb[pi] = *(const float4*)(sp + c * 4);
        *(float4*)kb[pi] = *(const float4*)(sp + 64 + c * 4);
        vb[pi] = sp[128 + gi];
        gb[pi] = *(const float4*)(sp + 192);

        // partial dot products over owned 4 columns
        float pv = 0.f, py = 0.f;
#pragma unroll
        for (int u = 0; u < 4; u++) {
            pv = fmaf(s[u], kb[bi][u], pv);
            py = fmaf(s[u], qb[bi][u], py);
        }
        // reduce over the 16 lanes of this row (pv/py chains interleave)
        pv += __shfl_xor_sync(0xffffffffu, pv, 1);
        py += __shfl_xor_sync(0xffffffffu, py, 1);
        pv += __shfl_xor_sync(0xffffffffu, pv, 2);
        py += __shfl_xor_sync(0xffffffffu, py, 2);
        pv += __shfl_xor_sync(0xffffffffu, pv, 4);
        py += __shfl_xor_sync(0xffffffffu, py, 4);
        pv += __shfl_xor_sync(0xffffffffu, pv, 8);
        py += __shfl_xor_sync(0xffffffffu, py, 8);

        if (c == 0) __stcs(ro + (size_t)l * 512, py);   // readout: PRE-update state

        const float d   = pv - vb[bi];
        const float td  = gb[bi].z * d;
        const float oma = 1.0f - gb[bi].x;
        const float e   = gb[bi].y;
#pragma unroll
        for (int u = 0; u < 4; u++) {
            m[u] = fmaf(e, m[u], -td * kb[bi][u]);   // eta*mom - theta*grad
            s[u] = fmaf(oma, s[u], m[u]);            // (1-alpha)*state + mom
        }

        __stcs((float4*)(ssq + (size_t)l * 32768), *(float4*)&s[0]);
        __stcs((float4*)(msq + (size_t)l * 32768), *(float4*)&m[0]);
    }
}

// ---------------------------------------------------------------------------
// Launch
// ---------------------------------------------------------------------------
extern "C" void kernel_launch(void* const* d_in, const int* in_sizes, int n_in,
                              void* d_out, int out_size) {
    const float* inputs   = (const float*)d_in[0];
    const float* Wq       = (const float*)d_in[1];
    const float* Wk       = (const float*)d_in[2];
    const float* Wv       = (const float*)d_in[3];
    const float* Wp       = (const float*)d_in[4];
    const float* bp       = (const float*)d_in[5];
    const float* prev_st  = (const float*)d_in[6];
    const float* prev_mom = (const float*)d_in[7];
    float* out = (float*)d_out;

    pack_weights_kernel<<<(D_ * NPAD + 255) / 256, 256>>>(Wq, Wk, Wv, Wp);
    sgemm_kernel<<<dim3(NPAD / 128, NROWS / 128), 256>>>(inputs);
    postproc_kernel<<<NROWS, 64>>>(bp);
    recurrence_kernel<<<B_ * H_ * 16, 64>>>(prev_st, prev_mom, out);
}